// round 15
// baseline (speedup 1.0000x reference)
#include <cuda_runtime.h>
#include <cuda_bf16.h>
#include <math.h>

// Problem constants
#define Sq    2048
#define HIDN  2048
#define NH    16
#define NKH   8
#define HD    128
#define GRP   2          // NH / NKH
#define EPSV  1e-6f
#define SCALEV 0.08838834764831845f   // 128^-0.5

#define NQ (NH * HD)     // 2048
#define NKV (NKH * HD)   // 1024
#define NQKV (NQ + 2 * NKV)  // 4096

// ---------------- static device scratch (allocation-free rule) ----------------
__device__ float g_q[Sq * NQ];
__device__ float g_k[Sq * NKV];
__device__ float g_v[Sq * NKV];
__device__ unsigned g_hs32[Sq * HIDN];       // tf32, [m][k]
__device__ unsigned g_wqkvT[HIDN * NQKV];    // tf32, [k][n]  (Wq|Wk|Wv)
__device__ unsigned g_woT[NQ * HIDN];        // tf32, [k][n]
__device__ unsigned g_q32[Sq * NQ];          // tf32 post norm+rope [m][k]
__device__ unsigned g_k32[Sq * NKV];         // tf32 post norm+rope
__device__ unsigned g_v32[Sq * NKV];         // tf32 raw v
__device__ unsigned g_y32[Sq * NQ];          // tf32 attention output [m][k]

// ---------------- tf32 helpers ----------------
__device__ __forceinline__ unsigned f2tf32(float f) {
    unsigned u;
    asm("cvt.rna.tf32.f32 %0, %1;" : "=r"(u) : "f"(f));
    return u;
}

__device__ __forceinline__ void mma_tf32(float c[4],
                                         unsigned a0, unsigned a1, unsigned a2, unsigned a3,
                                         unsigned b0, unsigned b1)
{
    asm volatile(
        "mma.sync.aligned.m16n8k8.row.col.f32.tf32.tf32.f32 "
        "{%0,%1,%2,%3}, {%4,%5,%6,%7}, {%8,%9}, {%0,%1,%2,%3};"
        : "+f"(c[0]), "+f"(c[1]), "+f"(c[2]), "+f"(c[3])
        : "r"(a0), "r"(a1), "r"(a2), "r"(a3), "r"(b0), "r"(b1));
}

__device__ __forceinline__ void cpa16(unsigned dst, const unsigned* src) {
    asm volatile("cp.async.cg.shared.global [%0], [%1], 16;\n" :: "r"(dst), "l"(src));
}
#define CP_COMMIT() asm volatile("cp.async.commit_group;\n")
#define CP_WAIT2()  asm volatile("cp.async.wait_group 2;\n")
#define CP_WAIT1()  asm volatile("cp.async.wait_group 1;\n")

// ---------------- elementwise fp32 -> tf32 convert (hs) ----------------
__global__ __launch_bounds__(256)
void convert_tf32_kernel(const float* __restrict__ in, unsigned* __restrict__ out, int n)
{
    int i = (blockIdx.x * 256 + threadIdx.x) * 4;
    if (i < n) {
        float4 v = *(const float4*)&in[i];
        *(uint4*)&out[i] = make_uint4(f2tf32(v.x), f2tf32(v.y), f2tf32(v.z), f2tf32(v.w));
    }
}

// ---------------- transpose + tf32 convert (4 weight tensors, one launch) ----------------
struct TDesc {
    const float* in;
    unsigned* out;
    int ldin, ldout, coloff, ny;
};

__global__ __launch_bounds__(256)
void transpose4_kernel(TDesc d0, TDesc d1, TDesc d2, TDesc d3)
{
    TDesc d;
    switch (blockIdx.z) {
        case 0: d = d0; break;
        case 1: d = d1; break;
        case 2: d = d2; break;
        default: d = d3; break;
    }
    if (blockIdx.y >= (unsigned)d.ny) return;

    __shared__ float t[128][33];   // [c-local][r-local]
    const int c0 = blockIdx.x * 128;
    const int r0 = blockIdx.y * 32;
    const int tx = threadIdx.x & 31;
    const int ty = threadIdx.x >> 5;   // 0..7

    #pragma unroll
    for (int tt = 0; tt < 4; tt++)
        #pragma unroll
        for (int i = 0; i < 32; i += 8)
            t[tt * 32 + tx][ty + i] =
                d.in[(size_t)(r0 + ty + i) * d.ldin + c0 + tt * 32 + tx];
    __syncthreads();
    #pragma unroll
    for (int tt = 0; tt < 4; tt++)
        #pragma unroll
        for (int i = 0; i < 32; i += 8)
            d.out[(size_t)(c0 + tt * 32 + ty + i) * d.ldout + d.coloff + r0 + tx] =
                f2tf32(t[tt * 32 + ty + i][tx]);
}

// ---------------- cp.async 3-stage pipelined tf32 GEMM ----------------
// A: M x K tf32 ROW-major (ldA) -> smem [m][k] pad GPA.
// B: N x K tf32 (pre-transposed to [k][n], ldB) -> smem [k][n] pad GPB.
// 128 threads = 4 warps, each warp a 64x64 quadrant of the 128x128 tile.
#define GPA 36
#define GPB 136
#define A_WORDS (128 * GPA)                 // 4608
#define B_WORDS (32 * GPB)                  // 4352
#define STG_WORDS (A_WORDS + B_WORDS)       // 8960
#define GEMM_SMEM (3 * STG_WORDS * 4)       // 107520 bytes

__device__ __forceinline__ void gemm_issue(unsigned smA, unsigned smB,
                                           const unsigned* At, const unsigned* Bt,
                                           int ldA, int ldB, int kt,
                                           int bm, int bn, int tid)
{
    #pragma unroll
    for (int i = 0; i < 8; i++) {
        int e   = tid + i * 128;
        int row = e >> 3;            // 0..127
        int kc  = (e & 7) * 4;       // 0..28
        cpa16(smA + (unsigned)(row * GPA + kc) * 4,
              At + (size_t)(bm + row) * ldA + kt * 32 + kc);
        int kk = e >> 5;             // 0..31
        int mc = e & 31;
        cpa16(smB + (unsigned)(kk * GPB + mc * 4) * 4,
              Bt + (size_t)(kt * 32 + kk) * ldB + bn + mc * 4);
    }
}

template <bool QKV>
__global__ __launch_bounds__(128, 2)
void mma_gemm(const unsigned* __restrict__ At, const unsigned* __restrict__ Bt,
              float* __restrict__ C0, float* __restrict__ C1, float* __restrict__ C2,
              unsigned* __restrict__ Ct,   // tf32 mirror for v region (QKV only)
              int ldA, int ldB, int K, int ldc_plain)
{
    extern __shared__ unsigned sm[];
    const unsigned smbase = (unsigned)__cvta_generic_to_shared(sm);

    const int bm = blockIdx.y * 128;
    const int bn = blockIdx.x * 128;

    const int tid  = threadIdx.x;
    const int lane = tid & 31;
    const int wid  = tid >> 5;          // 0..3
    const int wm   = (wid >> 1) * 64;   // warp row origin
    const int wn   = (wid & 1) * 64;    // warp col origin
    const int gid  = lane >> 2;
    const int tig  = lane & 3;

    float acc[4][8][4];
    #pragma unroll
    for (int mt = 0; mt < 4; mt++)
        #pragma unroll
        for (int nt = 0; nt < 8; nt++)
            #pragma unroll
            for (int r = 0; r < 4; r++)
                acc[mt][nt][r] = 0.0f;

    const int NT = K / 32;

    gemm_issue(smbase, smbase + A_WORDS * 4, At, Bt, ldA, ldB, 0, bm, bn, tid);
    CP_COMMIT();
    gemm_issue(smbase + STG_WORDS * 4, smbase + (STG_WORDS + A_WORDS) * 4,
               At, Bt, ldA, ldB, 1, bm, bn, tid);
    CP_COMMIT();

    for (int kt = 0; kt < NT; kt++) {
        __syncthreads();
        if (kt + 2 < NT) {
            int st = (kt + 2) % 3;
            gemm_issue(smbase + st * STG_WORDS * 4,
                       smbase + (st * STG_WORDS + A_WORDS) * 4,
                       At, Bt, ldA, ldB, kt + 2, bm, bn, tid);
        }
        CP_COMMIT();
        CP_WAIT2();
        __syncthreads();

        const unsigned* As = sm + (kt % 3) * STG_WORDS;
        const unsigned* Bs = As + A_WORDS;

        #pragma unroll
        for (int ks = 0; ks < 32; ks += 8) {
            unsigned a[4][4];
            #pragma unroll
            for (int mt = 0; mt < 4; mt++) {
                int mrow = wm + mt * 16;
                a[mt][0] = As[(mrow + gid    ) * GPA + ks + tig];
                a[mt][1] = As[(mrow + gid + 8) * GPA + ks + tig];
                a[mt][2] = As[(mrow + gid    ) * GPA + ks + tig + 4];
                a[mt][3] = As[(mrow + gid + 8) * GPA + ks + tig + 4];
            }
            unsigned b[8][2];
            #pragma unroll
            for (int nt = 0; nt < 8; nt++) {
                int ncol = wn + nt * 8;
                b[nt][0] = Bs[(ks + tig    ) * GPB + ncol + gid];
                b[nt][1] = Bs[(ks + tig + 4) * GPB + ncol + gid];
            }
            #pragma unroll
            for (int mt = 0; mt < 4; mt++)
                #pragma unroll
                for (int nt = 0; nt < 8; nt++)
                    mma_tf32(acc[mt][nt],
                             a[mt][0], a[mt][1], a[mt][2], a[mt][3],
                             b[nt][0], b[nt][1]);
        }
    }

    // ---- epilogue ----
    float* C;
    int ldc, cb;
    bool isv = false;
    if (QKV) {
        if (bn < NQ)            { C = C0; ldc = NQ;  cb = bn; }
        else if (bn < NQ + NKV) { C = C1; ldc = NKV; cb = bn - NQ; }
        else                    { C = C2; ldc = NKV; cb = bn - NQ - NKV; isv = true; }
    } else {
        C = C0; ldc = ldc_plain; cb = bn;
    }

    #pragma unroll
    for (int mt = 0; mt < 4; mt++) {
        #pragma unroll
        for (int nt = 0; nt < 8; nt++) {
            int r0 = bm + wm + mt * 16 + gid;
            int c0 = cb + wn + nt * 8 + tig * 2;
            *(float2*)&C[(size_t)r0       * ldc + c0] = make_float2(acc[mt][nt][0], acc[mt][nt][1]);
            *(float2*)&C[(size_t)(r0 + 8) * ldc + c0] = make_float2(acc[mt][nt][2], acc[mt][nt][3]);
            if (QKV && isv) {
                *(uint2*)&Ct[(size_t)r0       * ldc + c0] =
                    make_uint2(f2tf32(acc[mt][nt][0]), f2tf32(acc[mt][nt][1]));
                *(uint2*)&Ct[(size_t)(r0 + 8) * ldc + c0] =
                    make_uint2(f2tf32(acc[mt][nt][2]), f2tf32(acc[mt][nt][3]));
            }
        }
    }
}

// ---------------- fused flash attention (no-max softmax, paired q-blocks) ----------------
// RMSNorm bounds |s*SCALE| <= ~12.6, so exp() without max-shift is fp32-safe
// and algebraically identical after the final 1/sum normalization.
#define QS_PAD 132
#define KS_PAD 132
#define VS_PAD 136
#define FKV_WORDS (64 * KS_PAD + 64 * VS_PAD)          // one K+V stage = 17152
#define SMF_KV(st) (128 * QS_PAD + (st) * FKV_WORDS)   // K first, then V
#define SM_TOT ((128 * QS_PAD + 2 * FKV_WORDS) * 4)    // 204800 bytes

__device__ __forceinline__ void flash_issue_kv(unsigned smK, unsigned smV,
                                               const unsigned* k32, const unsigned* v32,
                                               int k0, int kh, int tid)
{
    #pragma unroll
    for (int i = 0; i < 8; i++) {
        int f   = tid + i * 256;
        int key = f >> 5;
        int c4  = f & 31;
        size_t goff = (size_t)(k0 + key) * NKV + kh * HD + c4 * 4;
        cpa16(smK + (unsigned)(key * KS_PAD + c4 * 4) * 4, k32 + goff);
        cpa16(smV + (unsigned)(key * VS_PAD + c4 * 4) * 4, v32 + goff);
    }
}

// grid (NH, 8): block processes q-blocks {15 - by (heavy), by (light)} -> 17 units each.
__global__ __launch_bounds__(256, 1)
void flash_kernel(const unsigned* __restrict__ q32,
                  const unsigned* __restrict__ k32,
                  const unsigned* __restrict__ v32,
                  unsigned* __restrict__ y32)
{
    extern __shared__ unsigned smf[];
    const unsigned smfb = (unsigned)__cvta_generic_to_shared(smf);
    unsigned* Qs = smf;

    const int head = blockIdx.x;
    const int kh   = head / GRP;

    const int tid  = threadIdx.x;
    const int lane = tid & 31;
    const int wid  = tid >> 5;
    const int gid  = lane >> 2;
    const int tig  = lane & 3;

    #pragma unroll 1
    for (int half = 0; half < 2; half++) {
        const int bq = half ? (int)blockIdx.y : (int)(15 - blockIdx.y);

        // ---- group: Q tile (128 x 128) + KV tile 0 ----
        #pragma unroll
        for (int i = 0; i < 16; i++) {
            int f   = tid + i * 256;
            int row = f >> 5;          // 0..127
            int c4  = f & 31;
            cpa16(smfb + (unsigned)(row * QS_PAD + c4 * 4) * 4,
                  q32 + (size_t)(bq * 128 + row) * NQ + head * HD + c4 * 4);
        }
        flash_issue_kv(smfb + SMF_KV(0) * 4, smfb + (SMF_KV(0) + 64 * KS_PAD) * 4,
                       k32, v32, 0, kh, tid);
        CP_COMMIT();

        float Oa[16][4];
        #pragma unroll
        for (int nt = 0; nt < 16; nt++)
            #pragma unroll
            for (int r = 0; r < 4; r++)
                Oa[nt][r] = 0.0f;
        float lrow0 = 0.0f, lrow1 = 0.0f;

        const int i0 = bq * 128 + wid * 16 + gid;
        const int nkb = 2 * (bq + 1);

        for (int kb = 0; kb < nkb; kb++) {
            const int k0 = kb * 64;

            if (kb + 1 < nkb) {
                int st = (kb + 1) & 1;
                flash_issue_kv(smfb + SMF_KV(st) * 4,
                               smfb + (SMF_KV(st) + 64 * KS_PAD) * 4,
                               k32, v32, k0 + 64, kh, tid);
            }
            CP_COMMIT();
            CP_WAIT1();
            __syncthreads();

            const unsigned* Ks = smf + SMF_KV(kb & 1);
            const unsigned* Vs = Ks + 64 * KS_PAD;

            // ---- S = Q @ K^T ----
            float s[8][4];
            #pragma unroll
            for (int nt = 0; nt < 8; nt++)
                #pragma unroll
                for (int r = 0; r < 4; r++)
                    s[nt][r] = 0.0f;

            #pragma unroll
            for (int ks = 0; ks < 128; ks += 8) {
                unsigned a0 = Qs[(wid * 16 + gid    ) * QS_PAD + ks + tig];
                unsigned a1 = Qs[(wid * 16 + gid + 8) * QS_PAD + ks + tig];
                unsigned a2 = Qs[(wid * 16 + gid    ) * QS_PAD + ks + tig + 4];
                unsigned a3 = Qs[(wid * 16 + gid + 8) * QS_PAD + ks + tig + 4];
                #pragma unroll
                for (int nt = 0; nt < 8; nt++) {
                    unsigned b0 = Ks[(nt * 8 + gid) * KS_PAD + ks + tig];
                    unsigned b1 = Ks[(nt * 8 + gid) * KS_PAD + ks + tig + 4];
                    mma_tf32(s[nt], a0, a1, a2, a3, b0, b1);
                }
            }

            // ---- scale + mask + exp (no max shift) + row-sum ----
            const bool diag = (k0 + 64 > bq * 128);
            float sum0 = 0.0f, sum1 = 0.0f;
            #pragma unroll
            for (int nt = 0; nt < 8; nt++) {
                int j = k0 + nt * 8 + tig * 2;
                #pragma unroll
                for (int r = 0; r < 4; r++) {
                    int jj = j + (r & 1);
                    int ii = i0 + ((r >> 1) << 3);
                    float val = s[nt][r] * SCALEV;
                    if (diag && jj > ii) val = -1e30f;
                    val = __expf(val);
                    s[nt][r] = val;
                }
                sum0 += s[nt][0] + s[nt][1];
                sum1 += s[nt][2] + s[nt][3];
            }
            sum0 += __shfl_xor_sync(0xffffffffu, sum0, 1);
            sum0 += __shfl_xor_sync(0xffffffffu, sum0, 2);
            sum1 += __shfl_xor_sync(0xffffffffu, sum1, 1);
            sum1 += __shfl_xor_sync(0xffffffffu, sum1, 2);
            lrow0 += sum0;
            lrow1 += sum1;

            // ---- O += P @ V ----
            const int srcA = (lane & ~3) | (tig >> 1);
            const int srcB = srcA + 2;
            const bool odd = (tig & 1);
            #pragma unroll
            for (int ks8 = 0; ks8 < 8; ks8++) {
                unsigned p0 = f2tf32(s[ks8][0]);
                unsigned p1 = f2tf32(s[ks8][1]);
                unsigned p2 = f2tf32(s[ks8][2]);
                unsigned p3 = f2tf32(s[ks8][3]);
                unsigned x0 = __shfl_sync(0xffffffffu, p0, srcA);
                unsigned x1 = __shfl_sync(0xffffffffu, p1, srcA);
                unsigned x2 = __shfl_sync(0xffffffffu, p2, srcA);
                unsigned x3 = __shfl_sync(0xffffffffu, p3, srcA);
                unsigned y0 = __shfl_sync(0xffffffffu, p0, srcB);
                unsigned y1 = __shfl_sync(0xffffffffu, p1, srcB);
                unsigned y2 = __shfl_sync(0xffffffffu, p2, srcB);
                unsigned y3 = __shfl_sync(0xffffffffu, p3, srcB);
                unsigned a0 = odd ? x1 : x0;
                unsigned a1 = odd ? x3 : x2;
                unsigned a2 = odd ? y1 : y0;
                unsigned a3 = odd ? y3 : y2;
                #pragma unroll
                for (int nt = 0; nt < 16; nt++) {
                    unsigned b0 = Vs[(ks8 * 8 + tig    ) * VS_PAD + nt * 8 + gid];
                    unsigned b1 = Vs[(ks8 * 8 + tig + 4) * VS_PAD + nt * 8 + gid];
                    mma_tf32(Oa[nt], a0, a1, a2, a3, b0, b1);
                }
            }
            __syncthreads();   // all warps done with stage (kb&1) before reuse
        }

        // ---- finalize & store this half (tf32, row-major) ----
        float inv0 = 1.0f / lrow0;
        float inv1 = 1.0f / lrow1;
        #pragma unroll
        for (int nt = 0; nt < 16; nt++) {
            int c0 = head * HD + nt * 8 + tig * 2;
            *(uint2*)&y32[(size_t)i0       * NQ + c0] =
                make_uint2(f2tf32(Oa[nt][0] * inv0), f2tf32(Oa[nt][1] * inv0));
            *(uint2*)&y32[(size_t)(i0 + 8) * NQ + c0] =
                make_uint2(f2tf32(Oa[nt][2] * inv1), f2tf32(Oa[nt][3] * inv1));
        }
    }
}

// ---------------- RMSNorm + RoPE (q and k in one launch) -> tf32 ----------------
__global__ __launch_bounds__(128)
void norm_rope_both_kernel(float* __restrict__ qx, unsigned* __restrict__ qt,
                           float* __restrict__ kx, unsigned* __restrict__ kt,
                           const float* __restrict__ qw, const float* __restrict__ kw,
                           const float* __restrict__ pcos, const float* __restrict__ psin)
{
    int b = blockIdx.x;
    float* x; unsigned* xt; const float* w; int nh; bool keep;
    if (b < Sq * NH / 4) {
        x = qx; xt = qt; w = qw; nh = NH; keep = false;
    } else {
        b -= Sq * NH / 4;
        x = kx; xt = kt; w = kw; nh = NKH; keep = true;
    }

    const int idx  = b * 4 + (threadIdx.x >> 5);
    const int lane = threadIdx.x & 31;
    const int s    = idx / nh;

    float* row = x + (size_t)idx * HD;
    float4 val = *(float4*)&row[lane * 4];

    float ssq = val.x * val.x + val.y * val.y + val.z * val.z + val.w * val.w;
    #pragma unroll
    for (int off = 16; off > 0; off >>= 1)
        ssq += __shfl_xor_sync(0xffffffffu, ssq, off);

    float r = rsqrtf(ssq * (1.0f / HD) + EPSV);
    float4 wv = *(const float4*)&w[lane * 4];
    float4 xn = make_float4(val.x * r * wv.x, val.y * r * wv.y,
                            val.z * r * wv.z, val.w * r * wv.w);

    float px = __shfl_xor_sync(0xffffffffu, xn.x, 16);
    float py = __shfl_xor_sync(0xffffffffu, xn.y, 16);
    float pz = __shfl_xor_sync(0xffffffffu, xn.z, 16);
    float pw = __shfl_xor_sync(0xffffffffu, xn.w, 16);

    const int cidx = (lane & 15) * 4;
    float4 cv = *(const float4*)&pcos[s * 64 + cidx];
    float4 sv = *(const float4*)&psin[s * 64 + cidx];

    float4 o;
    if (lane < 16) {
        o = make_float4(xn.x * cv.x - px * sv.x, xn.y * cv.y - py * sv.y,
                        xn.z * cv.z - pz * sv.z, xn.w * cv.w - pw * sv.w);
    } else {
        o = make_float4(px * sv.x + xn.x * cv.x, py * sv.y + xn.y * cv.y,
                        pz * sv.z + xn.z * cv.z, pw * sv.w + xn.w * cv.w);
    }
    if (keep)
        *(float4*)&row[lane * 4] = o;
    *(uint4*)&xt[(size_t)idx * HD + lane * 4] =
        make_uint4(f2tf32(o.x), f2tf32(o.y), f2tf32(o.z), f2tf32(o.w));
}

// ---------------- k_new / v_new tail copy ----------------
__global__ void tail_copy_kernel(const float* __restrict__ k,
                                 const float* __restrict__ v,
                                 float* __restrict__ out)
{
    int t = blockIdx.x * blockDim.x + threadIdx.x;
    const size_t base = (size_t)Sq * HIDN;
    if (t < NKV)
        out[base + t] = k[(size_t)(Sq - 1) * NKV + t];
    else
        out[base + t] = v[(size_t)(Sq - 1) * NKV + (t - NKV)];
}

// ---------------- launcher ----------------
extern "C" void kernel_launch(void* const* d_in, const int* in_sizes, int n_in,
                              void* d_out, int out_size)
{
    const float* hs   = (const float*)d_in[0];
    const float* pcos = (const float*)d_in[1];
    const float* psin = (const float*)d_in[2];
    // d_in[3] = atten_mask (causal, reproduced arithmetically)
    const float* Wq   = (const float*)d_in[4];
    const float* Wk   = (const float*)d_in[5];
    const float* Wv   = (const float*)d_in[6];
    const float* Wo   = (const float*)d_in[7];
    const float* qw   = (const float*)d_in[8];
    const float* kw   = (const float*)d_in[9];
    float* out = (float*)d_out;

    float *q, *k, *v;
    unsigned *hs32, *wqkvT, *woT, *q32, *k32, *v32, *y32;
    cudaGetSymbolAddress((void**)&q,     g_q);
    cudaGetSymbolAddress((void**)&k,     g_k);
    cudaGetSymbolAddress((void**)&v,     g_v);
    cudaGetSymbolAddress((void**)&hs32,  g_hs32);
    cudaGetSymbolAddress((void**)&wqkvT, g_wqkvT);
    cudaGetSymbolAddress((void**)&woT,   g_woT);
    cudaGetSymbolAddress((void**)&q32,   g_q32);
    cudaGetSymbolAddress((void**)&k32,   g_k32);
    cudaGetSymbolAddress((void**)&v32,   g_v32);
    cudaGetSymbolAddress((void**)&y32,   g_y32);

    cudaFuncSetAttribute(mma_gemm<true>,
                         cudaFuncAttributeMaxDynamicSharedMemorySize, GEMM_SMEM);
    cudaFuncSetAttribute(mma_gemm<false>,
                         cudaFuncAttributeMaxDynamicSharedMemorySize, GEMM_SMEM);
    cudaFuncSetAttribute(flash_kernel,
                         cudaFuncAttributeMaxDynamicSharedMemorySize, SM_TOT);

    // ---- hs elementwise convert + 4 weight transposes ----
    convert_tf32_kernel<<<Sq * HIDN / 1024, 256>>>(hs, hs32, Sq * HIDN);
    TDesc d1 = { Wq, wqkvT, HIDN, NQKV, 0,         64 };
    TDesc d2 = { Wk, wqkvT, HIDN, NQKV, NQ,        32 };
    TDesc d3 = { Wv, wqkvT, HIDN, NQKV, NQ + NKV,  32 };
    TDesc d4 = { Wo, woT,   NQ,   HIDN, 0,         64 };
    transpose4_kernel<<<dim3(16, 64, 4), 256>>>(d1, d2, d3, d4);

    // ---- fused QKV projection (A row-major; v also emitted as tf32) ----
    mma_gemm<true><<<dim3(NQKV / 128, Sq / 128), 128, GEMM_SMEM>>>(
        hs32, wqkvT, q, k, v, v32, HIDN, NQKV, HIDN, 0);

    // ---- RMSNorm + RoPE (q and k in one launch) ----
    norm_rope_both_kernel<<<(Sq * NH + Sq * NKH) / 4, 128>>>(
        q, q32, k, k32, qw, kw, pcos, psin);

    // ---- fused attention (no-max softmax, emits y32 directly) ----
    flash_kernel<<<dim3(NH, 8), 256, SM_TOT>>>(q32, k32, v32, y32);

    // ---- output projection (A = y32 row-major) ----
    mma_gemm<false><<<dim3(HIDN / 128, Sq / 128), 128, GEMM_SMEM>>>(
        y32, woT, out, nullptr, nullptr, nullptr, NQ, HIDN, NQ, HIDN);

    // ---- k_new / v_new ----
    tail_copy_kernel<<<8, 256>>>(k, v, out);
}

// round 17
// speedup vs baseline: 1.0382x; 1.0382x over previous
#include <cuda_runtime.h>
#include <cuda_bf16.h>
#include <math.h>

// Problem constants
#define Sq    2048
#define HIDN  2048
#define NH    16
#define NKH   8
#define HD    128
#define GRP   2          // NH / NKH
#define EPSV  1e-6f
#define SCALEV 0.08838834764831845f   // 128^-0.5

#define NQ (NH * HD)     // 2048
#define NKV (NKH * HD)   // 1024
#define NQKV (NQ + 2 * NKV)  // 4096

// ---------------- static device scratch (allocation-free rule) ----------------
__device__ float g_q[Sq * NQ];
__device__ float g_k[Sq * NKV];
__device__ float g_v[Sq * NKV];
__device__ float g_y[Sq * NQ];
__device__ unsigned g_hsT[HIDN * Sq];        // tf32, [k][m]
__device__ unsigned g_wqkvT[HIDN * NQKV];    // tf32, [k][n]  (Wq|Wk|Wv)
__device__ unsigned g_woT[NQ * HIDN];        // tf32, [k][n]
__device__ unsigned g_yT[NQ * Sq];           // tf32, [k][m]
__device__ unsigned g_q32[Sq * NQ];          // tf32 post norm+rope
__device__ unsigned g_k32[Sq * NKV];         // tf32 post norm+rope
__device__ unsigned g_v32[Sq * NKV];         // tf32 raw v

// ---------------- tf32 helpers ----------------
__device__ __forceinline__ unsigned f2tf32(float f) {
    unsigned u;
    asm("cvt.rna.tf32.f32 %0, %1;" : "=r"(u) : "f"(f));
    return u;
}

__device__ __forceinline__ void mma_tf32(float c[4],
                                         unsigned a0, unsigned a1, unsigned a2, unsigned a3,
                                         unsigned b0, unsigned b1)
{
    asm volatile(
        "mma.sync.aligned.m16n8k8.row.col.f32.tf32.tf32.f32 "
        "{%0,%1,%2,%3}, {%4,%5,%6,%7}, {%8,%9}, {%0,%1,%2,%3};"
        : "+f"(c[0]), "+f"(c[1]), "+f"(c[2]), "+f"(c[3])
        : "r"(a0), "r"(a1), "r"(a2), "r"(a3), "r"(b0), "r"(b1));
}

__device__ __forceinline__ void cpa16(unsigned dst, const unsigned* src) {
    asm volatile("cp.async.cg.shared.global [%0], [%1], 16;\n" :: "r"(dst), "l"(src));
}
#define CP_COMMIT() asm volatile("cp.async.commit_group;\n")
#define CP_WAIT2()  asm volatile("cp.async.wait_group 2;\n")
#define CP_WAIT1()  asm volatile("cp.async.wait_group 1;\n")

// ---------------- transpose + tf32 convert (5 tensors, one launch) ----------------
struct TDesc {
    const float* in;
    unsigned* out;
    int ldin, ldout, coloff, ny;
};

__global__ __launch_bounds__(256)
void transpose5_kernel(TDesc d0, TDesc d1, TDesc d2, TDesc d3, TDesc d4)
{
    TDesc d;
    switch (blockIdx.z) {
        case 0: d = d0; break;
        case 1: d = d1; break;
        case 2: d = d2; break;
        case 3: d = d3; break;
        default: d = d4; break;
    }
    if (blockIdx.y >= (unsigned)d.ny) return;

    __shared__ float t[128][33];   // [c-local][r-local]
    const int c0 = blockIdx.x * 128;
    const int r0 = blockIdx.y * 32;
    const int tx = threadIdx.x & 31;
    const int ty = threadIdx.x >> 5;   // 0..7

    #pragma unroll
    for (int tt = 0; tt < 4; tt++)
        #pragma unroll
        for (int i = 0; i < 32; i += 8)
            t[tt * 32 + tx][ty + i] =
                d.in[(size_t)(r0 + ty + i) * d.ldin + c0 + tt * 32 + tx];
    __syncthreads();
    #pragma unroll
    for (int tt = 0; tt < 4; tt++)
        #pragma unroll
        for (int i = 0; i < 32; i += 8)
            d.out[(size_t)(c0 + tt * 32 + ty + i) * d.ldout + d.coloff + r0 + tx] =
                f2tf32(t[tt * 32 + ty + i][tx]);
}

// single-tensor variant (for y -> yT)
__global__ __launch_bounds__(256)
void transpose_tf32_kernel(const float* __restrict__ in, unsigned* __restrict__ out,
                           int ldin, int ldout, int coloff)
{
    __shared__ float t[128][33];
    const int c0 = blockIdx.x * 128;
    const int r0 = blockIdx.y * 32;
    const int tx = threadIdx.x & 31;
    const int ty = threadIdx.x >> 5;

    #pragma unroll
    for (int tt = 0; tt < 4; tt++)
        #pragma unroll
        for (int i = 0; i < 32; i += 8)
            t[tt * 32 + tx][ty + i] =
                in[(size_t)(r0 + ty + i) * ldin + c0 + tt * 32 + tx];
    __syncthreads();
    #pragma unroll
    for (int tt = 0; tt < 4; tt++)
        #pragma unroll
        for (int i = 0; i < 32; i += 8)
            out[(size_t)(c0 + tt * 32 + ty + i) * ldout + coloff + r0 + tx] =
                f2tf32(t[tt * 32 + ty + i][tx]);
}

// ---------------- cp.async 3-stage pipelined tf32 GEMM ----------------
// 128 threads = 4 warps, each warp owns a 64x64 quadrant of the 128x128 tile.
#define GP 136
#define STG_WORDS (2 * 32 * GP)
#define NSTAGE 3
#define GEMM_SMEM (NSTAGE * STG_WORDS * 4)   // 104448 bytes

__device__ __forceinline__ void gemm_issue(unsigned smA, unsigned smB,
                                           const unsigned* At, const unsigned* Bt,
                                           int ldA, int ldB, int kt,
                                           int bm, int bn, int tid)
{
    #pragma unroll
    for (int i = 0; i < 8; i++) {
        int e  = tid + i * 128;
        int kk = e >> 5;
        int mc = e & 31;
        cpa16(smA + (unsigned)(kk * GP + mc * 4) * 4,
              At + (size_t)(kt * 32 + kk) * ldA + bm + mc * 4);
        cpa16(smB + (unsigned)(kk * GP + mc * 4) * 4,
              Bt + (size_t)(kt * 32 + kk) * ldB + bn + mc * 4);
    }
}

template <bool QKV>
__global__ __launch_bounds__(128, 2)
void mma_gemm(const unsigned* __restrict__ At, const unsigned* __restrict__ Bt,
              float* __restrict__ C0, float* __restrict__ C1, float* __restrict__ C2,
              unsigned* __restrict__ Ct,   // tf32 mirror for v region (QKV only)
              int ldA, int ldB, int K, int ldc_plain)
{
    extern __shared__ unsigned sm[];
    const unsigned smbase = (unsigned)__cvta_generic_to_shared(sm);

    const int bm = blockIdx.y * 128;
    const int bn = blockIdx.x * 128;

    const int tid  = threadIdx.x;
    const int lane = tid & 31;
    const int wid  = tid >> 5;          // 0..3
    const int wm   = (wid >> 1) * 64;   // warp row origin
    const int wn   = (wid & 1) * 64;    // warp col origin
    const int gid  = lane >> 2;
    const int tig  = lane & 3;

    float acc[4][8][4];
    #pragma unroll
    for (int mt = 0; mt < 4; mt++)
        #pragma unroll
        for (int nt = 0; nt < 8; nt++)
            #pragma unroll
            for (int r = 0; r < 4; r++)
                acc[mt][nt][r] = 0.0f;

    const int NT = K / 32;

    gemm_issue(smbase, smbase + 32 * GP * 4, At, Bt, ldA, ldB, 0, bm, bn, tid);
    CP_COMMIT();
    gemm_issue(smbase + STG_WORDS * 4, smbase + (STG_WORDS + 32 * GP) * 4,
               At, Bt, ldA, ldB, 1, bm, bn, tid);
    CP_COMMIT();

    for (int kt = 0; kt < NT; kt++) {
        __syncthreads();
        if (kt + 2 < NT) {
            int st = (kt + 2) % NSTAGE;
            gemm_issue(smbase + st * STG_WORDS * 4,
                       smbase + (st * STG_WORDS + 32 * GP) * 4,
                       At, Bt, ldA, ldB, kt + 2, bm, bn, tid);
        }
        CP_COMMIT();
        CP_WAIT2();
        __syncthreads();

        const unsigned* As = sm + (kt % NSTAGE) * STG_WORDS;
        const unsigned* Bs = As + 32 * GP;

        #pragma unroll
        for (int ks = 0; ks < 32; ks += 8) {
            unsigned a[4][4];
            #pragma unroll
            for (int mt = 0; mt < 4; mt++) {
                int mrow = wm + mt * 16;
                a[mt][0] = As[(ks + tig    ) * GP + mrow + gid];
                a[mt][1] = As[(ks + tig    ) * GP + mrow + gid + 8];
                a[mt][2] = As[(ks + tig + 4) * GP + mrow + gid];
                a[mt][3] = As[(ks + tig + 4) * GP + mrow + gid + 8];
            }
            unsigned b[8][2];
            #pragma unroll
            for (int nt = 0; nt < 8; nt++) {
                int ncol = wn + nt * 8;
                b[nt][0] = Bs[(ks + tig    ) * GP + ncol + gid];
                b[nt][1] = Bs[(ks + tig + 4) * GP + ncol + gid];
            }
            #pragma unroll
            for (int mt = 0; mt < 4; mt++)
                #pragma unroll
                for (int nt = 0; nt < 8; nt++)
                    mma_tf32(acc[mt][nt],
                             a[mt][0], a[mt][1], a[mt][2], a[mt][3],
                             b[nt][0], b[nt][1]);
        }
    }

    // ---- epilogue ----
    float* C;
    int ldc, cb;
    bool isv = false;
    if (QKV) {
        if (bn < NQ)            { C = C0; ldc = NQ;  cb = bn; }
        else if (bn < NQ + NKV) { C = C1; ldc = NKV; cb = bn - NQ; }
        else                    { C = C2; ldc = NKV; cb = bn - NQ - NKV; isv = true; }
    } else {
        C = C0; ldc = ldc_plain; cb = bn;
    }

    #pragma unroll
    for (int mt = 0; mt < 4; mt++) {
        #pragma unroll
        for (int nt = 0; nt < 8; nt++) {
            int r0 = bm + wm + mt * 16 + gid;
            int c0 = cb + wn + nt * 8 + tig * 2;
            *(float2*)&C[(size_t)r0       * ldc + c0] = make_float2(acc[mt][nt][0], acc[mt][nt][1]);
            *(float2*)&C[(size_t)(r0 + 8) * ldc + c0] = make_float2(acc[mt][nt][2], acc[mt][nt][3]);
            if (QKV && isv) {
                *(uint2*)&Ct[(size_t)r0       * ldc + c0] =
                    make_uint2(f2tf32(acc[mt][nt][0]), f2tf32(acc[mt][nt][1]));
                *(uint2*)&Ct[(size_t)(r0 + 8) * ldc + c0] =
                    make_uint2(f2tf32(acc[mt][nt][2]), f2tf32(acc[mt][nt][3]));
            }
        }
    }
}

// ---------------- fused flash attention (no-max softmax, paired q-blocks) ----------------
// RMSNorm bounds |s*SCALE| <= ~12.6, so exp() without max-shift is fp32-safe
// (sum <= 2048*e^12.5 ~ 5.5e8) and algebraically identical after 1/sum.
#define QS_PAD 132
#define KS_PAD 132
#define VS_PAD 136
#define FKV_WORDS (64 * KS_PAD + 64 * VS_PAD)          // one K+V stage = 17152
#define SMF_KV(st) (128 * QS_PAD + (st) * FKV_WORDS)   // K first, then V
#define SM_TOT ((128 * QS_PAD + 2 * FKV_WORDS) * 4)    // 204800 bytes

__device__ __forceinline__ void flash_issue_kv(unsigned smK, unsigned smV,
                                               const unsigned* k32, const unsigned* v32,
                                               int k0, int kh, int tid)
{
    #pragma unroll
    for (int i = 0; i < 8; i++) {
        int f   = tid + i * 256;
        int key = f >> 5;
        int c4  = f & 31;
        size_t goff = (size_t)(k0 + key) * NKV + kh * HD + c4 * 4;
        cpa16(smK + (unsigned)(key * KS_PAD + c4 * 4) * 4, k32 + goff);
        cpa16(smV + (unsigned)(key * VS_PAD + c4 * 4) * 4, v32 + goff);
    }
}

// grid (NH, 8): block processes q-blocks {15 - by (heavy), by (light)} -> 17 units each.
__global__ __launch_bounds__(256, 1)
void flash_kernel(const unsigned* __restrict__ q32,
                  const unsigned* __restrict__ k32,
                  const unsigned* __restrict__ v32,
                  float* __restrict__ y)
{
    extern __shared__ unsigned smf[];
    const unsigned smfb = (unsigned)__cvta_generic_to_shared(smf);
    unsigned* Qs = smf;

    const int head = blockIdx.x;
    const int kh   = head / GRP;

    const int tid  = threadIdx.x;
    const int lane = tid & 31;
    const int wid  = tid >> 5;
    const int gid  = lane >> 2;
    const int tig  = lane & 3;

    #pragma unroll 1
    for (int half = 0; half < 2; half++) {
        const int bq = half ? (int)blockIdx.y : (int)(15 - blockIdx.y);

        // ---- group: Q tile (128 x 128) + KV tile 0 ----
        #pragma unroll
        for (int i = 0; i < 16; i++) {
            int f   = tid + i * 256;
            int row = f >> 5;          // 0..127
            int c4  = f & 31;
            cpa16(smfb + (unsigned)(row * QS_PAD + c4 * 4) * 4,
                  q32 + (size_t)(bq * 128 + row) * NQ + head * HD + c4 * 4);
        }
        flash_issue_kv(smfb + SMF_KV(0) * 4, smfb + (SMF_KV(0) + 64 * KS_PAD) * 4,
                       k32, v32, 0, kh, tid);
        CP_COMMIT();

        float Oa[16][4];
        #pragma unroll
        for (int nt = 0; nt < 16; nt++)
            #pragma unroll
            for (int r = 0; r < 4; r++)
                Oa[nt][r] = 0.0f;
        float lrow0 = 0.0f, lrow1 = 0.0f;

        const int i0 = bq * 128 + wid * 16 + gid;
        const int nkb = 2 * (bq + 1);

        for (int kb = 0; kb < nkb; kb++) {
            const int k0 = kb * 64;

            if (kb + 1 < nkb) {
                int st = (kb + 1) & 1;
                flash_issue_kv(smfb + SMF_KV(st) * 4,
                               smfb + (SMF_KV(st) + 64 * KS_PAD) * 4,
                               k32, v32, k0 + 64, kh, tid);
            }
            CP_COMMIT();
            CP_WAIT1();
            __syncthreads();

            const unsigned* Ks = smf + SMF_KV(kb & 1);
            const unsigned* Vs = Ks + 64 * KS_PAD;

            // ---- S = Q @ K^T ----
            float s[8][4];
            #pragma unroll
            for (int nt = 0; nt < 8; nt++)
                #pragma unroll
                for (int r = 0; r < 4; r++)
                    s[nt][r] = 0.0f;

            #pragma unroll
            for (int ks = 0; ks < 128; ks += 8) {
                unsigned a0 = Qs[(wid * 16 + gid    ) * QS_PAD + ks + tig];
                unsigned a1 = Qs[(wid * 16 + gid + 8) * QS_PAD + ks + tig];
                unsigned a2 = Qs[(wid * 16 + gid    ) * QS_PAD + ks + tig + 4];
                unsigned a3 = Qs[(wid * 16 + gid + 8) * QS_PAD + ks + tig + 4];
                #pragma unroll
                for (int nt = 0; nt < 8; nt++) {
                    unsigned b0 = Ks[(nt * 8 + gid) * KS_PAD + ks + tig];
                    unsigned b1 = Ks[(nt * 8 + gid) * KS_PAD + ks + tig + 4];
                    mma_tf32(s[nt], a0, a1, a2, a3, b0, b1);
                }
            }

            // ---- scale + mask + exp (no max shift) + row-sum ----
            const bool diag = (k0 + 64 > bq * 128);
            float sum0 = 0.0f, sum1 = 0.0f;
            #pragma unroll
            for (int nt = 0; nt < 8; nt++) {
                int j = k0 + nt * 8 + tig * 2;
                #pragma unroll
                for (int r = 0; r < 4; r++) {
                    int jj = j + (r & 1);
                    int ii = i0 + ((r >> 1) << 3);
                    float val = s[nt][r] * SCALEV;
                    if (diag && jj > ii) val = -1e30f;
                    s[nt][r] = __expf(val);
                }
                sum0 += s[nt][0] + s[nt][1];
                sum1 += s[nt][2] + s[nt][3];
            }
            sum0 += __shfl_xor_sync(0xffffffffu, sum0, 1);
            sum0 += __shfl_xor_sync(0xffffffffu, sum0, 2);
            sum1 += __shfl_xor_sync(0xffffffffu, sum1, 1);
            sum1 += __shfl_xor_sync(0xffffffffu, sum1, 2);
            lrow0 += sum0;
            lrow1 += sum1;

            // ---- O += P @ V ----
            const int srcA = (lane & ~3) | (tig >> 1);
            const int srcB = srcA + 2;
            const bool odd = (tig & 1);
            #pragma unroll
            for (int ks8 = 0; ks8 < 8; ks8++) {
                unsigned p0 = f2tf32(s[ks8][0]);
                unsigned p1 = f2tf32(s[ks8][1]);
                unsigned p2 = f2tf32(s[ks8][2]);
                unsigned p3 = f2tf32(s[ks8][3]);
                unsigned x0 = __shfl_sync(0xffffffffu, p0, srcA);
                unsigned x1 = __shfl_sync(0xffffffffu, p1, srcA);
                unsigned x2 = __shfl_sync(0xffffffffu, p2, srcA);
                unsigned x3 = __shfl_sync(0xffffffffu, p3, srcA);
                unsigned y0 = __shfl_sync(0xffffffffu, p0, srcB);
                unsigned y1 = __shfl_sync(0xffffffffu, p1, srcB);
                unsigned y2 = __shfl_sync(0xffffffffu, p2, srcB);
                unsigned y3 = __shfl_sync(0xffffffffu, p3, srcB);
                unsigned a0 = odd ? x1 : x0;
                unsigned a1 = odd ? x3 : x2;
                unsigned a2 = odd ? y1 : y0;
                unsigned a3 = odd ? y3 : y2;
                #pragma unroll
                for (int nt = 0; nt < 16; nt++) {
                    unsigned b0 = Vs[(ks8 * 8 + tig    ) * VS_PAD + nt * 8 + gid];
                    unsigned b1 = Vs[(ks8 * 8 + tig + 4) * VS_PAD + nt * 8 + gid];
                    mma_tf32(Oa[nt], a0, a1, a2, a3, b0, b1);
                }
            }
            __syncthreads();   // all warps done with stage (kb&1) before reuse
        }

        // ---- finalize & store this half ----
        float inv0 = 1.0f / lrow0;
        float inv1 = 1.0f / lrow1;
        #pragma unroll
        for (int nt = 0; nt < 16; nt++) {
            int c0 = head * HD + nt * 8 + tig * 2;
            *(float2*)&y[(size_t)i0       * NQ + c0] = make_float2(Oa[nt][0] * inv0, Oa[nt][1] * inv0);
            *(float2*)&y[(size_t)(i0 + 8) * NQ + c0] = make_float2(Oa[nt][2] * inv1, Oa[nt][3] * inv1);
        }
    }
}

// ---------------- RMSNorm + RoPE (q and k in one launch) -> tf32 ----------------
__global__ __launch_bounds__(128)
void norm_rope_both_kernel(float* __restrict__ qx, unsigned* __restrict__ qt,
                           float* __restrict__ kx, unsigned* __restrict__ kt,
                           const float* __restrict__ qw, const float* __restrict__ kw,
                           const float* __restrict__ pcos, const float* __restrict__ psin)
{
    int b = blockIdx.x;
    float* x; unsigned* xt; const float* w; int nh; bool keep;
    if (b < Sq * NH / 4) {
        x = qx; xt = qt; w = qw; nh = NH; keep = false;
    } else {
        b -= Sq * NH / 4;
        x = kx; xt = kt; w = kw; nh = NKH; keep = true;
    }

    const int idx  = b * 4 + (threadIdx.x >> 5);
    const int lane = threadIdx.x & 31;
    const int s    = idx / nh;

    float* row = x + (size_t)idx * HD;
    float4 val = *(float4*)&row[lane * 4];

    float ssq = val.x * val.x + val.y * val.y + val.z * val.z + val.w * val.w;
    #pragma unroll
    for (int off = 16; off > 0; off >>= 1)
        ssq += __shfl_xor_sync(0xffffffffu, ssq, off);

    float r = rsqrtf(ssq * (1.0f / HD) + EPSV);
    float4 wv = *(const float4*)&w[lane * 4];
    float4 xn = make_float4(val.x * r * wv.x, val.y * r * wv.y,
                            val.z * r * wv.z, val.w * r * wv.w);

    float px = __shfl_xor_sync(0xffffffffu, xn.x, 16);
    float py = __shfl_xor_sync(0xffffffffu, xn.y, 16);
    float pz = __shfl_xor_sync(0xffffffffu, xn.z, 16);
    float pw = __shfl_xor_sync(0xffffffffu, xn.w, 16);

    const int cidx = (lane & 15) * 4;
    float4 cv = *(const float4*)&pcos[s * 64 + cidx];
    float4 sv = *(const float4*)&psin[s * 64 + cidx];

    float4 o;
    if (lane < 16) {
        o = make_float4(xn.x * cv.x - px * sv.x, xn.y * cv.y - py * sv.y,
                        xn.z * cv.z - pz * sv.z, xn.w * cv.w - pw * sv.w);
    } else {
        o = make_float4(px * sv.x + xn.x * cv.x, py * sv.y + xn.y * cv.y,
                        pz * sv.z + xn.z * cv.z, pw * sv.w + xn.w * cv.w);
    }
    if (keep)
        *(float4*)&row[lane * 4] = o;
    *(uint4*)&xt[(size_t)idx * HD + lane * 4] =
        make_uint4(f2tf32(o.x), f2tf32(o.y), f2tf32(o.z), f2tf32(o.w));
}

// ---------------- k_new / v_new tail copy ----------------
__global__ void tail_copy_kernel(const float* __restrict__ k,
                                 const float* __restrict__ v,
                                 float* __restrict__ out)
{
    int t = blockIdx.x * blockDim.x + threadIdx.x;
    const size_t base = (size_t)Sq * HIDN;
    if (t < NKV)
        out[base + t] = k[(size_t)(Sq - 1) * NKV + t];
    else
        out[base + t] = v[(size_t)(Sq - 1) * NKV + (t - NKV)];
}

// ---------------- launcher ----------------
extern "C" void kernel_launch(void* const* d_in, const int* in_sizes, int n_in,
                              void* d_out, int out_size)
{
    const float* hs   = (const float*)d_in[0];
    const float* pcos = (const float*)d_in[1];
    const float* psin = (const float*)d_in[2];
    // d_in[3] = atten_mask (causal, reproduced arithmetically)
    const float* Wq   = (const float*)d_in[4];
    const float* Wk   = (const float*)d_in[5];
    const float* Wv   = (const float*)d_in[6];
    const float* Wo   = (const float*)d_in[7];
    const float* qw   = (const float*)d_in[8];
    const float* kw   = (const float*)d_in[9];
    float* out = (float*)d_out;

    float *q, *k, *v, *y;
    unsigned *hsT, *wqkvT, *woT, *yT, *q32, *k32, *v32;
    cudaGetSymbolAddress((void**)&q,     g_q);
    cudaGetSymbolAddress((void**)&k,     g_k);
    cudaGetSymbolAddress((void**)&v,     g_v);
    cudaGetSymbolAddress((void**)&y,     g_y);
    cudaGetSymbolAddress((void**)&hsT,   g_hsT);
    cudaGetSymbolAddress((void**)&wqkvT, g_wqkvT);
    cudaGetSymbolAddress((void**)&woT,   g_woT);
    cudaGetSymbolAddress((void**)&yT,    g_yT);
    cudaGetSymbolAddress((void**)&q32,   g_q32);
    cudaGetSymbolAddress((void**)&k32,   g_k32);
    cudaGetSymbolAddress((void**)&v32,   g_v32);

    cudaFuncSetAttribute(mma_gemm<true>,
                         cudaFuncAttributeMaxDynamicSharedMemorySize, GEMM_SMEM);
    cudaFuncSetAttribute(mma_gemm<false>,
                         cudaFuncAttributeMaxDynamicSharedMemorySize, GEMM_SMEM);
    cudaFuncSetAttribute(flash_kernel,
                         cudaFuncAttributeMaxDynamicSharedMemorySize, SM_TOT);

    // ---- all 5 input transposes in ONE launch ----
    TDesc d0 = { hs, hsT,   HIDN, Sq,   0,         64 };
    TDesc d1 = { Wq, wqkvT, HIDN, NQKV, 0,         64 };
    TDesc d2 = { Wk, wqkvT, HIDN, NQKV, NQ,        32 };
    TDesc d3 = { Wv, wqkvT, HIDN, NQKV, NQ + NKV,  32 };
    TDesc d4 = { Wo, woT,   NQ,   HIDN, 0,         64 };
    transpose5_kernel<<<dim3(16, 64, 5), 256>>>(d0, d1, d2, d3, d4);

    // ---- fused QKV projection (v also emitted as tf32) ----
    mma_gemm<true><<<dim3(NQKV / 128, Sq / 128), 128, GEMM_SMEM>>>(
        hsT, wqkvT, q, k, v, v32, Sq, NQKV, HIDN, 0);

    // ---- RMSNorm + RoPE (q and k in one launch) ----
    norm_rope_both_kernel<<<(Sq * NH + Sq * NKH) / 4, 128>>>(
        q, q32, k, k32, qw, kw, pcos, psin);

    // ---- fused attention (no-max softmax, paired q-blocks) ----
    flash_kernel<<<dim3(NH, 8), 256, SM_TOT>>>(q32, k32, v32, y);

    // ---- y -> yT, then output projection ----
    transpose_tf32_kernel<<<dim3(16, 64), 256>>>(y, yT, NQ, Sq, 0);
    mma_gemm<false><<<dim3(HIDN / 128, Sq / 128), 128, GEMM_SMEM>>>(
        yT, woT, out, nullptr, nullptr, nullptr, Sq, HIDN, NQ, HIDN);

    // ---- k_new / v_new ----
    tail_copy_kernel<<<8, 256>>>(k, v, out);
}